// round 5
// baseline (speedup 1.0000x reference)
#include <cuda_runtime.h>
#include <cuda_bf16.h>
#include <math.h>
#include <stdint.h>

// Problem constants
#define S_LEN 2048
#define HID   2048
#define NH    16
#define HD    128
#define QKV_N 6144   // 3*HID
#define EPS   1e-5f

// ---------------- scratch (device globals: allocation-free) ----------------
__device__ float         g_mixed  [S_LEN * QKV_N];  // fp32 QKV for attention
__device__ __nv_bfloat16 g_lnx_hi [S_LEN * HID];
__device__ __nv_bfloat16 g_lnx_lo [S_LEN * HID];
__device__ __nv_bfloat16 g_wqkv_hi[QKV_N * HID];
__device__ __nv_bfloat16 g_wqkv_lo[QKV_N * HID];
__device__ __nv_bfloat16 g_ctx_hi [S_LEN * HID];
__device__ __nv_bfloat16 g_ctx_lo [S_LEN * HID];
__device__ __nv_bfloat16 g_wproj_hi[HID * HID];
__device__ __nv_bfloat16 g_wproj_lo[HID * HID];

// ---------------- helpers ----------------
__device__ __forceinline__ uint32_t smem_u32(const void* p) {
    uint32_t a;
    asm("{ .reg .u64 t; cvta.to.shared.u64 t, %1; cvt.u32.u64 %0, t; }" : "=r"(a) : "l"(p));
    return a;
}
__device__ __forceinline__ void ldm_x4(uint32_t* r, uint32_t addr) {
    asm volatile("ldmatrix.sync.aligned.m8n8.x4.shared.b16 {%0,%1,%2,%3}, [%4];"
        : "=r"(r[0]), "=r"(r[1]), "=r"(r[2]), "=r"(r[3]) : "r"(addr));
}
__device__ __forceinline__ void mma_bf16(float* d, const uint32_t* a, uint32_t b0, uint32_t b1) {
    asm volatile("mma.sync.aligned.m16n8k16.row.col.f32.bf16.bf16.f32 "
        "{%0,%1,%2,%3}, {%4,%5,%6,%7}, {%8,%9}, {%0,%1,%2,%3};"
        : "+f"(d[0]), "+f"(d[1]), "+f"(d[2]), "+f"(d[3])
        : "r"(a[0]), "r"(a[1]), "r"(a[2]), "r"(a[3]), "r"(b0), "r"(b1));
}
__device__ __forceinline__ void cp16(uint32_t saddr, const void* g) {
    asm volatile("cp.async.cg.shared.global [%0], [%1], 16;" :: "r"(saddr), "l"(g));
}
#define CP_COMMIT() asm volatile("cp.async.commit_group;" ::: "memory")
#define CP_WAIT1()  asm volatile("cp.async.wait_group 1;" ::: "memory")
#define CP_WAIT0()  asm volatile("cp.async.wait_group 0;" ::: "memory")

// ---------------- fp32 -> bf16 hi/lo split helpers ----------------
__device__ __forceinline__ void split4_store(float4 v, __nv_bfloat16* hp, __nv_bfloat16* lp) {
    __nv_bfloat16 h0 = __float2bfloat16(v.x), h1 = __float2bfloat16(v.y);
    __nv_bfloat16 h2 = __float2bfloat16(v.z), h3 = __float2bfloat16(v.w);
    __nv_bfloat16 l0 = __float2bfloat16(v.x - __bfloat162float(h0));
    __nv_bfloat16 l1 = __float2bfloat16(v.y - __bfloat162float(h1));
    __nv_bfloat16 l2 = __float2bfloat16(v.z - __bfloat162float(h2));
    __nv_bfloat16 l3 = __float2bfloat16(v.w - __bfloat162float(h3));
    __nv_bfloat162 H0 = __halves2bfloat162(h0, h1), H1 = __halves2bfloat162(h2, h3);
    __nv_bfloat162 L0 = __halves2bfloat162(l0, l1), L1 = __halves2bfloat162(l2, l3);
    *(uint2*)hp = make_uint2(*(uint32_t*)&H0, *(uint32_t*)&H1);
    *(uint2*)lp = make_uint2(*(uint32_t*)&L0, *(uint32_t*)&L1);
}

// ---------------- LayerNorm: one block per row, writes bf16 hi/lo ----------------
__global__ __launch_bounds__(256)
void layernorm_kernel(const float* __restrict__ x,
                      const float* __restrict__ w,
                      const float* __restrict__ b) {
    int s = blockIdx.x;
    int tid = threadIdx.x;
    const float* row = x + (size_t)s * HID;

    float4 a = *(const float4*)(row + tid * 4);
    float4 c = *(const float4*)(row + 1024 + tid * 4);

    float s1 = a.x + a.y + a.z + a.w + c.x + c.y + c.z + c.w;
    float s2 = a.x*a.x + a.y*a.y + a.z*a.z + a.w*a.w
             + c.x*c.x + c.y*c.y + c.z*c.z + c.w*c.w;

    #pragma unroll
    for (int off = 16; off; off >>= 1) {
        s1 += __shfl_xor_sync(0xffffffffu, s1, off);
        s2 += __shfl_xor_sync(0xffffffffu, s2, off);
    }
    __shared__ float r1[8], r2[8];
    int wrp = tid >> 5, lane = tid & 31;
    if (lane == 0) { r1[wrp] = s1; r2[wrp] = s2; }
    __syncthreads();
    if (tid == 0) {
        float t1 = 0.f, t2 = 0.f;
        #pragma unroll
        for (int i = 0; i < 8; i++) { t1 += r1[i]; t2 += r2[i]; }
        r1[0] = t1; r2[0] = t2;
    }
    __syncthreads();
    float mu  = r1[0] * (1.f / HID);
    float var = r2[0] * (1.f / HID) - mu * mu;
    float rs  = rsqrtf(var + EPS);

    size_t rbase = (size_t)s * HID;
    int c0 = tid * 4;
    float4 w0 = *(const float4*)(w + c0);
    float4 b0 = *(const float4*)(b + c0);
    float4 o0;
    o0.x = (a.x - mu) * rs * w0.x + b0.x;
    o0.y = (a.y - mu) * rs * w0.y + b0.y;
    o0.z = (a.z - mu) * rs * w0.z + b0.z;
    o0.w = (a.w - mu) * rs * w0.w + b0.w;
    split4_store(o0, g_lnx_hi + rbase + c0, g_lnx_lo + rbase + c0);

    int c1 = 1024 + tid * 4;
    float4 w1 = *(const float4*)(w + c1);
    float4 b1 = *(const float4*)(b + c1);
    float4 o1;
    o1.x = (c.x - mu) * rs * w1.x + b1.x;
    o1.y = (c.y - mu) * rs * w1.y + b1.y;
    o1.z = (c.z - mu) * rs * w1.z + b1.z;
    o1.w = (c.w - mu) * rs * w1.w + b1.w;
    split4_store(o1, g_lnx_hi + rbase + c1, g_lnx_lo + rbase + c1);
}

// ---------------- weight split kernel ----------------
__global__ __launch_bounds__(256)
void splitw_kernel(const float* __restrict__ x, int which, int n) {
    __nv_bfloat16* hi = which ? g_wproj_hi : g_wqkv_hi;
    __nv_bfloat16* lo = which ? g_wproj_lo : g_wqkv_lo;
    int i = (blockIdx.x * 256 + threadIdx.x) * 4;
    if (i < n) {
        float4 v = *(const float4*)(x + i);
        split4_store(v, hi + i, lo + i);
    }
}

// ---------------- mma.sync bf16x3 GEMM: C[M,N] = A[M,K]*B[N,K]^T + bias ------
// CTA tile 128x128, BK=32. 8 warps, each 64x32 (4 mtiles x 4 n8-tiles).
// Smem per stage: A-hi 8KB | A-lo 8KB | B-hi 8KB | B-lo 8KB = 32KB. 2 stages.
// Each 8KB region: 128 rows x 32 cols bf16 as 16x16 tiles (512B each):
//   off = ((r>>4)*2 + (c>>4))*512 + (r&15)*32 + (((c>>3)&1) ^ ((r>>2)&1))*16 + (c&7)*2
#define BK 32
#define STAGE_BYTES 32768
#define A_HI_OFF 0
#define A_LO_OFF 8192
#define B_HI_OFF 16384
#define B_LO_OFF 24576
#define GSMEM (2 * STAGE_BYTES)

__global__ __launch_bounds__(256, 1)
void gemm_mma_kernel(int which, const float* __restrict__ bias,
                     float* __restrict__ Cout, int ldc) {
    extern __shared__ __align__(1024) char smem[];
    const __nv_bfloat16 *Ahi, *Alo, *Bhi, *Blo;
    float* Cp;
    if (which == 0) { Ahi = g_lnx_hi; Alo = g_lnx_lo; Bhi = g_wqkv_hi; Blo = g_wqkv_lo; Cp = g_mixed; }
    else            { Ahi = g_ctx_hi; Alo = g_ctx_lo; Bhi = g_wproj_hi; Blo = g_wproj_lo; Cp = Cout; }

    const int NCHUNK = HID / BK;  // 64
    uint32_t sb = smem_u32(smem);
    int tid = threadIdx.x, wid = tid >> 5, lane = tid & 31;
    int row0 = blockIdx.y * 128, col0 = blockIdx.x * 128;
    int wm = wid >> 2, wn = wid & 3;

    // cp.async mapping: 512 16B-chunks per 8KB region; thread handles v = tid, tid+256
    // v -> row r = v>>2 (0..127), 16B-chunk c16 = v&3 (k-offset c16*8)
    int soff[2]; size_t ga[2], gb[2];
    #pragma unroll
    for (int j = 0; j < 2; j++) {
        int v = tid + j * 256;
        int r = v >> 2, c16 = v & 3, tr = r & 15;
        soff[j] = ((r >> 4) * 2 + (c16 >> 1)) * 512 + tr * 32
                + (((c16 & 1) ^ ((tr >> 2) & 1))) * 16;
        ga[j] = (size_t)(row0 + r) * HID + c16 * 8;
        gb[j] = (size_t)(col0 + r) * HID + c16 * 8;
    }

    float acc[4][4][4];
    #pragma unroll
    for (int i = 0; i < 4; i++)
        #pragma unroll
        for (int j = 0; j < 4; j++)
            #pragma unroll
            for (int q = 0; q < 4; q++) acc[i][j][q] = 0.f;

    // ldmatrix per-lane address offset within a 512B 16x16 tile
    int lr = lane & 15, lch = lane >> 4;
    int laneoff = lr * 32 + ((lch ^ ((lr >> 2) & 1))) * 16;

    // prologue: issue chunks 0 and 1
    #pragma unroll
    for (int c = 0; c < 2; c++) {
        uint32_t base = sb + c * STAGE_BYTES;
        int k0 = c * BK;
        #pragma unroll
        for (int j = 0; j < 2; j++) {
            cp16(base + A_HI_OFF + soff[j], Ahi + ga[j] + k0);
            cp16(base + A_LO_OFF + soff[j], Alo + ga[j] + k0);
            cp16(base + B_HI_OFF + soff[j], Bhi + gb[j] + k0);
            cp16(base + B_LO_OFF + soff[j], Blo + gb[j] + k0);
        }
        CP_COMMIT();
    }

    for (int c = 0; c < NCHUNK; c++) {
        if (c >= NCHUNK - 2) CP_WAIT0(); else CP_WAIT1();
        __syncthreads();
        uint32_t stg = sb + (c & 1) * STAGE_BYTES;

        #pragma unroll
        for (int kt = 0; kt < 2; kt++) {
            uint32_t aT0 = stg + ((wm * 4 + 0) * 2 + kt) * 512 + laneoff;
            uint32_t bT0 = stg + ((wn * 2 + 0) * 2 + kt) * 512 + laneoff;
            uint32_t aH[4][4], aL[4][4], bH[2][4], bL[2][4];
            #pragma unroll
            for (int mt = 0; mt < 4; mt++) ldm_x4(aH[mt], aT0 + A_HI_OFF + mt * 1024);
            #pragma unroll
            for (int j = 0; j < 2; j++)  ldm_x4(bH[j], bT0 + B_HI_OFF + j * 1024);
            // Ah * Bh
            #pragma unroll
            for (int mt = 0; mt < 4; mt++)
                #pragma unroll
                for (int j = 0; j < 2; j++) {
                    mma_bf16(acc[mt][j*2+0], aH[mt], bH[j][0], bH[j][2]);
                    mma_bf16(acc[mt][j*2+1], aH[mt], bH[j][1], bH[j][3]);
                }
            // Ah * Bl
            #pragma unroll
            for (int j = 0; j < 2; j++)  ldm_x4(bL[j], bT0 + B_LO_OFF + j * 1024);
            #pragma unroll
            for (int mt = 0; mt < 4; mt++)
                #pragma unroll
                for (int j = 0; j < 2; j++) {
                    mma_bf16(acc[mt][j*2+0], aH[mt], bL[j][0], bL[j][2]);
                    mma_bf16(acc[mt][j*2+1], aH[mt], bL[j][1], bL[j][3]);
                }
            // Al * Bh
            #pragma unroll
            for (int mt = 0; mt < 4; mt++) ldm_x4(aL[mt], aT0 + A_LO_OFF + mt * 1024);
            #pragma unroll
            for (int mt = 0; mt < 4; mt++)
                #pragma unroll
                for (int j = 0; j < 2; j++) {
                    mma_bf16(acc[mt][j*2+0], aL[mt], bH[j][0], bH[j][2]);
                    mma_bf16(acc[mt][j*2+1], aL[mt], bH[j][1], bH[j][3]);
                }
        }
        __syncthreads();
        if (c + 2 < NCHUNK) {
            uint32_t base = sb + (c & 1) * STAGE_BYTES;
            int k0 = (c + 2) * BK;
            #pragma unroll
            for (int j = 0; j < 2; j++) {
                cp16(base + A_HI_OFF + soff[j], Ahi + ga[j] + k0);
                cp16(base + A_LO_OFF + soff[j], Alo + ga[j] + k0);
                cp16(base + B_HI_OFF + soff[j], Bhi + gb[j] + k0);
                cp16(base + B_LO_OFF + soff[j], Blo + gb[j] + k0);
            }
            CP_COMMIT();
        }
    }

    // epilogue: fragment (lane l): rows rg, rg+8; cols cg, cg+1 per n8 tile
    int rg = lane >> 2, cg = (lane & 3) * 2;
    #pragma unroll
    for (int mt = 0; mt < 4; mt++) {
        int row = row0 + wm * 64 + mt * 16 + rg;
        #pragma unroll
        for (int n8 = 0; n8 < 4; n8++) {
            int col = col0 + wn * 32 + n8 * 8 + cg;
            float b0 = bias[col], b1 = bias[col + 1];
            float2 v0 = make_float2(acc[mt][n8][0] + b0, acc[mt][n8][1] + b1);
            float2 v1 = make_float2(acc[mt][n8][2] + b0, acc[mt][n8][3] + b1);
            *(float2*)(Cp + (size_t)row * ldc + col)       = v0;
            *(float2*)(Cp + (size_t)(row + 8) * ldc + col) = v1;
        }
    }
}

// ---------------- causal flash attention (fp32, registers) ----------------
#define AM 64
#define AN 32

__global__ __launch_bounds__(256)
void attn_kernel() {
    __shared__ float Ks[AN][HD];
    __shared__ float Vs[AN][HD];

    int h   = blockIdx.y;
    int q0  = blockIdx.x * AM;
    int tid = threadIdx.x;
    int m   = tid >> 2;
    int p   = tid & 3;
    int qi  = q0 + m;

    const float scale = 0.08838834764831845f;  // 1/sqrt(128)

    float q[32], o[32];
    const float* qptr = g_mixed + (size_t)qi * QKV_N + h * HD + p * 4;
    #pragma unroll
    for (int i = 0; i < 8; i++) {
        float4 v = *(const float4*)(qptr + i * 16);
        q[i*4+0] = v.x * scale; q[i*4+1] = v.y * scale;
        q[i*4+2] = v.z * scale; q[i*4+3] = v.w * scale;
        o[i*4+0] = 0.f; o[i*4+1] = 0.f; o[i*4+2] = 0.f; o[i*4+3] = 0.f;
    }

    float m_i = -INFINITY, l_i = 0.f;

    int lrow = tid >> 3;
    int lcol = (tid & 7) * 16;

    int kend = q0 + AM;
    for (int kt0 = 0; kt0 < kend; kt0 += AN) {
        const float* kp = g_mixed + (size_t)(kt0 + lrow) * QKV_N + HID + h * HD + lcol;
        const float* vp = kp + HID;
        #pragma unroll
        for (int j = 0; j < 4; j++) {
            *(float4*)&Ks[lrow][lcol + j * 4] = *(const float4*)(kp + j * 4);
            *(float4*)&Vs[lrow][lcol + j * 4] = *(const float4*)(vp + j * 4);
        }
        __syncthreads();

        float sc[AN];
        #pragma unroll
        for (int n = 0; n < AN; n++) {
            float part = 0.f;
            #pragma unroll
            for (int i = 0; i < 8; i++) {
                float4 kv = *(const float4*)&Ks[n][i * 16 + p * 4];
                part += q[i*4+0] * kv.x + q[i*4+1] * kv.y
                      + q[i*4+2] * kv.z + q[i*4+3] * kv.w;
            }
            part += __shfl_xor_sync(0xffffffffu, part, 1);
            part += __shfl_xor_sync(0xffffffffu, part, 2);
            sc[n] = (kt0 + n <= qi) ? part : -INFINITY;
        }

        float tmax = m_i;
        #pragma unroll
        for (int n = 0; n < AN; n++) tmax = fmaxf(tmax, sc[n]);
        float corr = __expf(m_i - tmax);
        m_i = tmax;
        float ps = 0.f;
        #pragma unroll
        for (int n = 0; n < AN; n++) { sc[n] = __expf(sc[n] - m_i); ps += sc[n]; }
        l_i = l_i * corr + ps;

        #pragma unroll
        for (int ii = 0; ii < 32; ii++) o[ii] *= corr;

        #pragma unroll
        for (int n = 0; n < AN; n++) {
            float pn = sc[n];
            #pragma unroll
            for (int i = 0; i < 8; i++) {
                float4 vv = *(const float4*)&Vs[n][i * 16 + p * 4];
                o[i*4+0] += pn * vv.x; o[i*4+1] += pn * vv.y;
                o[i*4+2] += pn * vv.z; o[i*4+3] += pn * vv.w;
            }
        }
        __syncthreads();
    }

    float inv = 1.f / l_i;
    size_t obase = (size_t)qi * HID + h * HD + p * 4;
    #pragma unroll
    for (int i = 0; i < 8; i++) {
        float4 v;
        v.x = o[i*4+0] * inv; v.y = o[i*4+1] * inv;
        v.z = o[i*4+2] * inv; v.w = o[i*4+3] * inv;
        split4_store(v, g_ctx_hi + obase + i * 16, g_ctx_lo + obase + i * 16);
    }
}

// ---------------- launch ----------------
extern "C" void kernel_launch(void* const* d_in, const int* in_sizes, int n_in,
                              void* d_out, int out_size) {
    const float* hs   = (const float*)d_in[0];
    const float* lw   = (const float*)d_in[1];
    const float* lb   = (const float*)d_in[2];
    const float* qkvw = (const float*)d_in[3];
    const float* qkvb = (const float*)d_in[4];
    const float* pw   = (const float*)d_in[5];
    const float* pb   = (const float*)d_in[6];
    float* out = (float*)d_out;

    cudaFuncSetAttribute(gemm_mma_kernel, cudaFuncAttributeMaxDynamicSharedMemorySize, GSMEM);

    layernorm_kernel<<<S_LEN, 256>>>(hs, lw, lb);
    splitw_kernel<<<(QKV_N * HID / 4) / 256, 256>>>(qkvw, 0, QKV_N * HID);
    splitw_kernel<<<(HID * HID / 4) / 256, 256>>>(pw, 1, HID * HID);
    gemm_mma_kernel<<<dim3(QKV_N / 128, S_LEN / 128), 256, GSMEM>>>(0, qkvb, nullptr, QKV_N);
    attn_kernel<<<dim3(S_LEN / AM, NH), 256>>>();
    gemm_mma_kernel<<<dim3(HID / 128, S_LEN / 128), 256, GSMEM>>>(1, pb, out, HID);
}

// round 7
// speedup vs baseline: 3.1785x; 3.1785x over previous
#include <cuda_runtime.h>
#include <cuda_bf16.h>
#include <math.h>
#include <stdint.h>

#define S_LEN 2048
#define HID   2048
#define NH    16
#define HD    128
#define QKV_N 6144
#define EPS   1e-5f
#define QSCALE 0.08838834764831845f

__device__ __nv_bfloat16 g_lnx_hi [S_LEN * HID];
__device__ __nv_bfloat16 g_lnx_lo [S_LEN * HID];
__device__ __nv_bfloat16 g_wqkv_hi[QKV_N * HID];
__device__ __nv_bfloat16 g_wqkv_lo[QKV_N * HID];
__device__ __nv_bfloat16 g_wproj_hi[HID * HID];
__device__ __nv_bfloat16 g_wproj_lo[HID * HID];
__device__ __nv_bfloat16 g_q_hi[S_LEN * HID];
__device__ __nv_bfloat16 g_q_lo[S_LEN * HID];
__device__ __nv_bfloat16 g_k_hi[S_LEN * HID];
__device__ __nv_bfloat16 g_k_lo[S_LEN * HID];
__device__ __nv_bfloat16 g_v_hi[S_LEN * HID];
__device__ __nv_bfloat16 g_v_lo[S_LEN * HID];
__device__ __nv_bfloat16 g_ctx_hi[S_LEN * HID];
__device__ __nv_bfloat16 g_ctx_lo[S_LEN * HID];

__device__ __forceinline__ uint32_t smem_u32(const void* p) {
    uint32_t a;
    asm("{ .reg .u64 t; cvta.to.shared.u64 t, %1; cvt.u32.u64 %0, t; }" : "=r"(a) : "l"(p));
    return a;
}
__device__ __forceinline__ void ldm_x4(uint32_t* r, uint32_t addr) {
    asm volatile("ldmatrix.sync.aligned.m8n8.x4.shared.b16 {%0,%1,%2,%3}, [%4];"
        : "=r"(r[0]), "=r"(r[1]), "=r"(r[2]), "=r"(r[3]) : "r"(addr));
}
__device__ __forceinline__ void ldm_x4t(uint32_t* r, uint32_t addr) {
    asm volatile("ldmatrix.sync.aligned.m8n8.x4.trans.shared.b16 {%0,%1,%2,%3}, [%4];"
        : "=r"(r[0]), "=r"(r[1]), "=r"(r[2]), "=r"(r[3]) : "r"(addr));
}
__device__ __forceinline__ void mma_bf16(float* d, const uint32_t* a, uint32_t b0, uint32_t b1) {
    asm volatile("mma.sync.aligned.m16n8k16.row.col.f32.bf16.bf16.f32 "
        "{%0,%1,%2,%3}, {%4,%5,%6,%7}, {%8,%9}, {%0,%1,%2,%3};"
        : "+f"(d[0]), "+f"(d[1]), "+f"(d[2]), "+f"(d[3])
        : "r"(a[0]), "r"(a[1]), "r"(a[2]), "r"(a[3]), "r"(b0), "r"(b1));
}
__device__ __forceinline__ void cp16(uint32_t saddr, const void* g) {
    asm volatile("cp.async.cg.shared.global [%0], [%1], 16;" :: "r"(saddr), "l"(g));
}
#define CP_COMMIT() asm volatile("cp.async.commit_group;" ::: "memory")
#define CP_WAIT1()  asm volatile("cp.async.wait_group 1;" ::: "memory")
#define CP_WAIT0()  asm volatile("cp.async.wait_group 0;" ::: "memory")

__device__ __forceinline__ void split_pack(float a, float b, uint32_t& hi, uint32_t& lo) {
    __nv_bfloat162 h = __floats2bfloat162_rn(a, b);
    hi = *(uint32_t*)&h;
    __nv_bfloat162 l = __floats2bfloat162_rn(a - __bfloat162float(h.x),
                                             b - __bfloat162float(h.y));
    lo = *(uint32_t*)&l;
}
__device__ __forceinline__ void split4_store(float4 v, __nv_bfloat16* hp, __nv_bfloat16* lp) {
    uint32_t h0, l0, h1, l1;
    split_pack(v.x, v.y, h0, l0);
    split_pack(v.z, v.w, h1, l1);
    *(uint2*)hp = make_uint2(h0, h1);
    *(uint2*)lp = make_uint2(l0, l1);
}

// ---------------- LayerNorm ----------------
__global__ __launch_bounds__(256)
void layernorm_kernel(const float* __restrict__ x, const float* __restrict__ w,
                      const float* __restrict__ b) {
    int s = blockIdx.x, tid = threadIdx.x;
    const float* row = x + (size_t)s * HID;
    float4 a = *(const float4*)(row + tid * 4);
    float4 c = *(const float4*)(row + 1024 + tid * 4);
    float s1 = a.x + a.y + a.z + a.w + c.x + c.y + c.z + c.w;
    float s2 = a.x*a.x + a.y*a.y + a.z*a.z + a.w*a.w
             + c.x*c.x + c.y*c.y + c.z*c.z + c.w*c.w;
    #pragma unroll
    for (int off = 16; off; off >>= 1) {
        s1 += __shfl_xor_sync(0xffffffffu, s1, off);
        s2 += __shfl_xor_sync(0xffffffffu, s2, off);
    }
    __shared__ float r1[8], r2[8];
    int wrp = tid >> 5, lane = tid & 31;
    if (lane == 0) { r1[wrp] = s1; r2[wrp] = s2; }
    __syncthreads();
    if (tid == 0) {
        float t1 = 0.f, t2 = 0.f;
        #pragma unroll
        for (int i = 0; i < 8; i++) { t1 += r1[i]; t2 += r2[i]; }
        r1[0] = t1; r2[0] = t2;
    }
    __syncthreads();
    float mu = r1[0] * (1.f / HID);
    float var = r2[0] * (1.f / HID) - mu * mu;
    float rs = rsqrtf(var + EPS);
    size_t rbase = (size_t)s * HID;
    int c0 = tid * 4;
    float4 w0 = *(const float4*)(w + c0), b0 = *(const float4*)(b + c0);
    float4 o0 = make_float4((a.x-mu)*rs*w0.x+b0.x, (a.y-mu)*rs*w0.y+b0.y,
                            (a.z-mu)*rs*w0.z+b0.z, (a.w-mu)*rs*w0.w+b0.w);
    split4_store(o0, g_lnx_hi + rbase + c0, g_lnx_lo + rbase + c0);
    int c1 = 1024 + tid * 4;
    float4 w1 = *(const float4*)(w + c1), b1 = *(const float4*)(b + c1);
    float4 o1 = make_float4((c.x-mu)*rs*w1.x+b1.x, (c.y-mu)*rs*w1.y+b1.y,
                            (c.z-mu)*rs*w1.z+b1.z, (c.w-mu)*rs*w1.w+b1.w);
    split4_store(o1, g_lnx_hi + rbase + c1, g_lnx_lo + rbase + c1);
}

__global__ __launch_bounds__(256)
void splitw_kernel(const float* __restrict__ x, int which, int n) {
    __nv_bfloat16* hi = which ? g_wproj_hi : g_wqkv_hi;
    __nv_bfloat16* lo = which ? g_wproj_lo : g_wqkv_lo;
    int i = (blockIdx.x * 256 + threadIdx.x) * 4;
    if (i < n) split4_store(*(const float4*)(x + i), hi + i, lo + i);
}

// ---------------- GEMM (epilogue which==0 -> split q/k/v) ----------------
#define BK 32
#define STAGE_BYTES 32768
#define A_HI_OFF 0
#define A_LO_OFF 8192
#define B_HI_OFF 16384
#define B_LO_OFF 24576
#define GSMEM (2 * STAGE_BYTES)

__global__ __launch_bounds__(256, 1)
void gemm_mma_kernel(int which, const float* __restrict__ bias,
                     float* __restrict__ Cout, int ldc) {
    extern __shared__ __align__(1024) char smem[];
    const __nv_bfloat16 *Ahi, *Alo, *Bhi, *Blo;
    if (which == 0) { Ahi = g_lnx_hi; Alo = g_lnx_lo; Bhi = g_wqkv_hi; Blo = g_wqkv_lo; }
    else            { Ahi = g_ctx_hi; Alo = g_ctx_lo; Bhi = g_wproj_hi; Blo = g_wproj_lo; }
    const int NCHUNK = HID / BK;
    uint32_t sb = smem_u32(smem);
    int tid = threadIdx.x, wid = tid >> 5, lane = tid & 31;
    int row0 = blockIdx.y * 128, col0 = blockIdx.x * 128;
    int wm = wid >> 2, wn = wid & 3;

    int soff[2]; size_t ga[2], gb[2];
    #pragma unroll
    for (int j = 0; j < 2; j++) {
        int v = tid + j * 256;
        int r = v >> 2, c16 = v & 3, tr = r & 15;
        soff[j] = ((r >> 4) * 2 + (c16 >> 1)) * 512 + tr * 32
                + (((c16 & 1) ^ ((tr >> 2) & 1))) * 16;
        ga[j] = (size_t)(row0 + r) * HID + c16 * 8;
        gb[j] = (size_t)(col0 + r) * HID + c16 * 8;
    }
    float acc[4][4][4];
    #pragma unroll
    for (int i = 0; i < 4; i++)
        #pragma unroll
        for (int j = 0; j < 4; j++)
            #pragma unroll
            for (int q = 0; q < 4; q++) acc[i][j][q] = 0.f;
    int lr = lane & 15, lch = lane >> 4;
    int laneoff = lr * 32 + ((lch ^ ((lr >> 2) & 1))) * 16;

    #pragma unroll
    for (int c = 0; c < 2; c++) {
        uint32_t base = sb + c * STAGE_BYTES;
        int k0 = c * BK;
        #pragma unroll
        for (int j = 0; j < 2; j++) {
            cp16(base + A_HI_OFF + soff[j], Ahi + ga[j] + k0);
            cp16(base + A_LO_OFF + soff[j], Alo + ga[j] + k0);
            cp16(base + B_HI_OFF + soff[j], Bhi + gb[j] + k0);
            cp16(base + B_LO_OFF + soff[j], Blo + gb[j] + k0);
        }
        CP_COMMIT();
    }
    for (int c = 0; c < NCHUNK; c++) {
        if (c >= NCHUNK - 2) CP_WAIT0(); else CP_WAIT1();
        __syncthreads();
        uint32_t stg = sb + (c & 1) * STAGE_BYTES;
        #pragma unroll
        for (int kt = 0; kt < 2; kt++) {
            uint32_t aT0 = stg + ((wm * 4) * 2 + kt) * 512 + laneoff;
            uint32_t bT0 = stg + ((wn * 2) * 2 + kt) * 512 + laneoff;
            uint32_t aH[4][4], aL[4][4], bH[2][4], bL[2][4];
            #pragma unroll
            for (int mt = 0; mt < 4; mt++) ldm_x4(aH[mt], aT0 + A_HI_OFF + mt * 1024);
            #pragma unroll
            for (int j = 0; j < 2; j++)  ldm_x4(bH[j], bT0 + B_HI_OFF + j * 1024);
            #pragma unroll
            for (int mt = 0; mt < 4; mt++)
                #pragma unroll
                for (int j = 0; j < 2; j++) {
                    mma_bf16(acc[mt][j*2+0], aH[mt], bH[j][0], bH[j][2]);
                    mma_bf16(acc[mt][j*2+1], aH[mt], bH[j][1], bH[j][3]);
                }
            #pragma unroll
            for (int j = 0; j < 2; j++)  ldm_x4(bL[j], bT0 + B_LO_OFF + j * 1024);
            #pragma unroll
            for (int mt = 0; mt < 4; mt++)
                #pragma unroll
                for (int j = 0; j < 2; j++) {
                    mma_bf16(acc[mt][j*2+0], aH[mt], bL[j][0], bL[j][2]);
                    mma_bf16(acc[mt][j*2+1], aH[mt], bL[j][1], bL[j][3]);
                }
            #pragma unroll
            for (int mt = 0; mt < 4; mt++) ldm_x4(aL[mt], aT0 + A_LO_OFF + mt * 1024);
            #pragma unroll
            for (int mt = 0; mt < 4; mt++)
                #pragma unroll
                for (int j = 0; j < 2; j++) {
                    mma_bf16(acc[mt][j*2+0], aL[mt], bH[j][0], bH[j][2]);
                    mma_bf16(acc[mt][j*2+1], aL[mt], bH[j][1], bH[j][3]);
                }
        }
        __syncthreads();
        if (c + 2 < NCHUNK) {
            uint32_t base = sb + (c & 1) * STAGE_BYTES;
            int k0 = (c + 2) * BK;
            #pragma unroll
            for (int j = 0; j < 2; j++) {
                cp16(base + A_HI_OFF + soff[j], Ahi + ga[j] + k0);
                cp16(base + A_LO_OFF + soff[j], Alo + ga[j] + k0);
                cp16(base + B_HI_OFF + soff[j], Bhi + gb[j] + k0);
                cp16(base + B_LO_OFF + soff[j], Blo + gb[j] + k0);
            }
            CP_COMMIT();
        }
    }
    int rg = lane >> 2, cg = (lane & 3) * 2;
    #pragma unroll
    for (int mt = 0; mt < 4; mt++) {
        int row = row0 + wm * 64 + mt * 16 + rg;
        #pragma unroll
        for (int n8 = 0; n8 < 4; n8++) {
            int col = col0 + wn * 32 + n8 * 8 + cg;
            float b0 = bias[col], b1 = bias[col + 1];
            if (which == 0) {
                int seg = col >> 11, cs = col & 2047;
                float sc = (seg == 0) ? QSCALE : 1.f;
                __nv_bfloat16 *hp = (seg == 0) ? g_q_hi : (seg == 1) ? g_k_hi : g_v_hi;
                __nv_bfloat16 *lp = (seg == 0) ? g_q_lo : (seg == 1) ? g_k_lo : g_v_lo;
                uint32_t hi, lo;
                split_pack((acc[mt][n8][0]+b0)*sc, (acc[mt][n8][1]+b1)*sc, hi, lo);
                *(uint32_t*)(hp + (size_t)row * HID + cs) = hi;
                *(uint32_t*)(lp + (size_t)row * HID + cs) = lo;
                split_pack((acc[mt][n8][2]+b0)*sc, (acc[mt][n8][3]+b1)*sc, hi, lo);
                *(uint32_t*)(hp + (size_t)(row + 8) * HID + cs) = hi;
                *(uint32_t*)(lp + (size_t)(row + 8) * HID + cs) = lo;
            } else {
                *(float2*)(Cout + (size_t)row * ldc + col) =
                    make_float2(acc[mt][n8][0]+b0, acc[mt][n8][1]+b1);
                *(float2*)(Cout + (size_t)(row + 8) * ldc + col) =
                    make_float2(acc[mt][n8][2]+b0, acc[mt][n8][3]+b1);
            }
        }
    }
}

// ---------------- FA2 attention, mma.sync bf16x3 ----------------
#define QH_OFF 0
#define QL_OFF 32768
#define ST_OFF 65536
#define ST_STRIDE 65536
#define AKH 0
#define AKL 16384
#define AVH 32768
#define AVL 49152
#define ASMEM (ST_OFF + 2 * ST_STRIDE)

__global__ __launch_bounds__(256, 1)
void attn_mma_kernel() {
    extern __shared__ __align__(1024) char smem[];
    uint32_t sb = smem_u32(smem);
    int tid = threadIdx.x, wid = tid >> 5, lane = tid & 31, l15 = lane & 15;
    int h = blockIdx.y;
    int qb = (int)gridDim.x - 1 - (int)blockIdx.x;
    int q0 = qb * 128;
    int ntiles = qb * 2 + 2;
    size_t hoff = (size_t)h * HD;

    int qs[8]; size_t qg[8];
    #pragma unroll
    for (int j = 0; j < 8; j++) {
        int v = tid + j * 256;
        int r = v >> 4, c16 = v & 15, tc = c16 >> 1;
        qs[j] = ((r >> 4) * 8 + tc) * 512 + (((r & 15) ^ tc) * 32)
              + (((c16 & 1) ^ ((r >> 2) & 1)) * 16);
        qg[j] = (size_t)(q0 + r) * HID + hoff + c16 * 8;
    }
    int ks[4]; size_t kg[4];
    #pragma unroll
    for (int j = 0; j < 4; j++) {
        int v = tid + j * 256;
        int r = v >> 4, c16 = v & 15, tc = c16 >> 1;
        ks[j] = ((r >> 4) * 8 + tc) * 512 + (((r & 15) ^ tc) * 32)
              + (((c16 & 1) ^ ((r >> 2) & 1)) * 16);
        kg[j] = (size_t)r * HID + hoff + c16 * 8;
    }

    #pragma unroll
    for (int j = 0; j < 8; j++) {
        cp16(sb + QH_OFF + qs[j], g_q_hi + qg[j]);
        cp16(sb + QL_OFF + qs[j], g_q_lo + qg[j]);
    }
    CP_COMMIT();
    #pragma unroll
    for (int t = 0; t < 2; t++) {
        uint32_t stb = sb + ST_OFF + t * ST_STRIDE;
        size_t kvb = (size_t)(t * 64) * HID;
        #pragma unroll
        for (int j = 0; j < 4; j++) {
            cp16(stb + AKH + ks[j], g_k_hi + kvb + kg[j]);
            cp16(stb + AKL + ks[j], g_k_lo + kvb + kg[j]);
            cp16(stb + AVH + ks[j], g_v_hi + kvb + kg[j]);
            cp16(stb + AVL + ks[j], g_v_lo + kvb + kg[j]);
        }
        CP_COMMIT();
    }

    int slotoff = ((lane >> 4) ^ ((lane >> 2) & 1)) * 16;
    int gr = q0 + wid * 16 + (lane >> 2);
    int colb = 2 * (lane & 3);

    float o[16][4];
    #pragma unroll
    for (int i = 0; i < 16; i++)
        #pragma unroll
        for (int j = 0; j < 4; j++) o[i][j] = 0.f;
    float m0 = -INFINITY, m1 = -INFINITY, l0 = 0.f, l1 = 0.f;

    for (int t = 0; t < ntiles; t++) {
        if (t >= ntiles - 2) CP_WAIT0(); else CP_WAIT1();
        __syncthreads();
        uint32_t stb = sb + ST_OFF + (t & 1) * ST_STRIDE;
        int kt0 = t * 64;
        bool active = (q0 + wid * 16 + 15) >= kt0;

        if (active) {
            float s[8][4];
            #pragma unroll
            for (int i = 0; i < 8; i++)
                #pragma unroll
                for (int j = 0; j < 4; j++) s[i][j] = 0.f;

            #pragma unroll
            for (int kc = 0; kc < 8; kc++) {
                int tl = ((l15 ^ kc) * 32) + slotoff;
                uint32_t qh[4], ql[4], kh[4][4], kl[4][4];
                ldm_x4(qh, sb + QH_OFF + (wid * 8 + kc) * 512 + tl);
                ldm_x4(ql, sb + QL_OFF + (wid * 8 + kc) * 512 + tl);
                #pragma unroll
                for (int ng = 0; ng < 4; ng++) ldm_x4(kh[ng], stb + AKH + (ng * 8 + kc) * 512 + tl);
                #pragma unroll
                for (int ng = 0; ng < 4; ng++) ldm_x4(kl[ng], stb + AKL + (ng * 8 + kc) * 512 + tl);
                #pragma unroll
                for (int ng = 0; ng < 4; ng++) {
                    mma_bf16(s[2*ng],   qh, kh[ng][0], kh[ng][2]);
                    mma_bf16(s[2*ng+1], qh, kh[ng][1], kh[ng][3]);
                    mma_bf16(s[2*ng],   qh, kl[ng][0], kl[ng][2]);
                    mma_bf16(s[2*ng+1], qh, kl[ng][1], kl[ng][3]);
                    mma_bf16(s[2*ng],   ql, kh[ng][0], kh[ng][2]);
                    mma_bf16(s[2*ng+1], ql, kh[ng][1], kh[ng][3]);
                }
            }

            if (kt0 + 63 > gr) {
                #pragma unroll
                for (int t8 = 0; t8 < 8; t8++) {
                    int col = kt0 + t8 * 8 + colb;
                    if (col > gr)         s[t8][0] = -INFINITY;
                    if (col + 1 > gr)     s[t8][1] = -INFINITY;
                    if (col > gr + 8)     s[t8][2] = -INFINITY;
                    if (col + 1 > gr + 8) s[t8][3] = -INFINITY;
                }
            }

            float tm0 = m0, tm1 = m1;
            #pragma unroll
            for (int t8 = 0; t8 < 8; t8++) {
                tm0 = fmaxf(tm0, fmaxf(s[t8][0], s[t8][1]));
                tm1 = fmaxf(tm1, fmaxf(s[t8][2], s[t8][3]));
            }
            tm0 = fmaxf(tm0, __shfl_xor_sync(0xffffffffu, tm0, 1));
            tm0 = fmaxf(tm0, __shfl_xor_sync(0xffffffffu, tm0, 2));
            tm1 = fmaxf(tm1, __shfl_xor_sync(0xffffffffu, tm1, 1));
            tm1 = fmaxf(tm1, __shfl_xor_sync(0xffffffffu, tm1, 2));
            float c0 = __expf(m0 - tm0), c1 = __expf(m1 - tm1);
            m0 = tm0; m1 = tm1;
            float rs0 = 0.f, rs1 = 0.f;
            #pragma unroll
            for (int t8 = 0; t8 < 8; t8++) {
                s[t8][0] = __expf(s[t8][0] - m0); rs0 += s[t8][0];
                s[t8][1] = __expf(s[t8][1] - m0); rs0 += s[t8][1];
                s[t8][2] = __expf(s[t8][2] - m1); rs1 += s[t8][2];
                s[t8][3] = __expf(s[t8][3] - m1); rs1 += s[t8][3];
            }
            rs0 += __shfl_xor_sync(0xffffffffu, rs0, 1);
            rs0 += __shfl_xor_sync(0xffffffffu, rs0, 2);
            rs1 += __shfl_xor_sync(0xffffffffu, rs1, 1);
            rs1 += __shfl_xor_sync(0xffffffffu, rs1, 2);
            l0 = l0 * c0 + rs0;
            l1 = l1 * c1 + rs1;
            #pragma unroll
            for (int i = 0; i < 16; i++) {
                o[i][0] *= c0; o[i][1] *= c0; o[i][2] *= c1; o[i][3] *= c1;
            }

            #pragma unroll
            for (int kc2 = 0; kc2 < 4; kc2++) {
                uint32_t ph[4], pl[4];
                split_pack(s[2*kc2][0],   s[2*kc2][1],   ph[0], pl[0]);
                split_pack(s[2*kc2][2],   s[2*kc2][3],   ph[1], pl[1]);
                split_pack(s[2*kc2+1][0], s[2*kc2+1][1], ph[2], pl[2]);
                split_pack(s[2*kc2+1][2], s[2*kc2+1][3], ph[3], pl[3]);
                #pragma unroll
                for (int dd = 0; dd < 8; dd++) {
                    int tl = ((l15 ^ dd) * 32) + slotoff;
                    uint32_t vh[4], vl[4];
                    ldm_x4t(vh, stb + AVH + (kc2 * 8 + dd) * 512 + tl);
                    ldm_x4t(vl, stb + AVL + (kc2 * 8 + dd) * 512 + tl);
                    mma_bf16(o[dd*2],   ph, vh[0], vh[1]);
                    mma_bf16(o[dd*2+1], ph, vh[2], vh[3]);
                    mma_bf16(o[dd*2],   ph, vl[0], vl[1]);
                    mma_bf16(o[dd*2+1], ph, vl[2], vl[3]);
                    mma_bf16(o[dd*2],   pl, vh[0], vh[1]);
                    mma_bf16(o[dd*2+1], pl, vh[2], vh[3]);
                }
            }
        }
        __syncthreads();
        if (t + 2 < ntiles) {
            uint32_t stb2 = sb + ST_OFF + (t & 1) * ST_STRIDE;
            size_t kvb = (size_t)((t + 2) * 64) * HID;
            #pragma unroll
            for (int j = 0; j < 4; j++) {
                cp16(stb2 + AKH + ks[j], g_k_hi + kvb + kg[j]);
                cp16(stb2 + AKL + ks[j], g_k_lo + kvb + kg[j]);
                cp16(stb2 + AVH + ks[j], g_v_hi + kvb + kg[j]);
                cp16(stb2 + AVL + ks[j], g_v_lo + kvb + kg[j]);
            }
            CP_COMMIT();
        }
    }

    float inv0 = 1.f / l0, inv1 = 1.f / l1;
    size_t ob0 = (size_t)gr * HID + hoff + colb;
    size_t ob1 = (size_t)(gr + 8) * HID + hoff + colb;
    #pragma unroll
    for (int n8 = 0; n8 < 16; n8++) {
        uint32_t hi, lo;
        split_pack(o[n8][0] * inv0, o[n8][1] * inv0, hi, lo);
        *(uint32_t*)(g_ctx_hi + ob0 + n8 * 8) = hi;
        *(uint32_t*)(g_ctx_lo + ob0 + n8 * 8) = lo;
        split_pack(o[n8][2] * inv1, o[n8][3] * inv1, hi, lo);
        *(uint32_t*)(g_ctx_hi + ob1 + n8 * 8) = hi;
        *(uint32_t*)(g_ctx_lo + ob1 + n8 * 8) = lo;
    }
}

extern "C" void kernel_launch(void* const* d_in, const int* in_sizes, int n_in,
                              void* d_out, int out_size) {
    const float* hs   = (const float*)d_in[0];
    const float* lw   = (const float*)d_in[1];
    const float* lb   = (const float*)d_in[2];
    const float* qkvw = (const float*)d_in[3];
    const float* qkvb = (const float*)d_in[4];
    const float* pw   = (const float*)d_in[5];
    const float* pb   = (const float*)d_in[6];
    float* out = (float*)d_out;

    cudaFuncSetAttribute(gemm_mma_kernel, cudaFuncAttributeMaxDynamicSharedMemorySize, GSMEM);
    cudaFuncSetAttribute(attn_mma_kernel, cudaFuncAttributeMaxDynamicSharedMemorySize, ASMEM);

    layernorm_kernel<<<S_LEN, 256>>>(hs, lw, lb);
    splitw_kernel<<<(QKV_N * HID / 4) / 256, 256>>>(qkvw, 0, QKV_N * HID);
    splitw_kernel<<<(HID * HID / 4) / 256, 256>>>(pw, 1, HID * HID);
    gemm_mma_kernel<<<dim3(QKV_N / 128, S_LEN / 128), 256, GSMEM>>>(0, qkvb, nullptr, QKV_N);
    attn_mma_kernel<<<dim3(S_LEN / 128, NH), 256, ASMEM>>>();
    gemm_mma_kernel<<<dim3(HID / 128, S_LEN / 128), 256, GSMEM>>>(1, pb, out, HID);
}

// round 9
// speedup vs baseline: 3.4381x; 1.0817x over previous
#include <cuda_runtime.h>
#include <cuda_bf16.h>
#include <math.h>
#include <stdint.h>

#define S_LEN 2048
#define HID   2048
#define NH    16
#define HD    128
#define QKV_N 6144
#define EPS   1e-5f
#define QSCALE 0.08838834764831845f

__device__ __nv_bfloat16 g_lnx_hi [S_LEN * HID];
__device__ __nv_bfloat16 g_lnx_lo [S_LEN * HID];
__device__ __nv_bfloat16 g_wqkv_hi[QKV_N * HID];
__device__ __nv_bfloat16 g_wqkv_lo[QKV_N * HID];
__device__ __nv_bfloat16 g_wproj_hi[HID * HID];
__device__ __nv_bfloat16 g_wproj_lo[HID * HID];
__device__ __nv_bfloat16 g_q_hi[S_LEN * HID];
__device__ __nv_bfloat16 g_q_lo[S_LEN * HID];
__device__ __nv_bfloat16 g_k_hi[S_LEN * HID];
__device__ __nv_bfloat16 g_k_lo[S_LEN * HID];
__device__ __nv_bfloat16 g_v_hi[S_LEN * HID];
__device__ __nv_bfloat16 g_v_lo[S_LEN * HID];
__device__ __nv_bfloat16 g_ctx_hi[S_LEN * HID];
__device__ __nv_bfloat16 g_ctx_lo[S_LEN * HID];

__device__ __forceinline__ uint32_t smem_u32(const void* p) {
    uint32_t a;
    asm("{ .reg .u64 t; cvta.to.shared.u64 t, %1; cvt.u32.u64 %0, t; }" : "=r"(a) : "l"(p));
    return a;
}
__device__ __forceinline__ void ldm_x4(uint32_t* r, uint32_t addr) {
    asm volatile("ldmatrix.sync.aligned.m8n8.x4.shared.b16 {%0,%1,%2,%3}, [%4];"
        : "=r"(r[0]), "=r"(r[1]), "=r"(r[2]), "=r"(r[3]) : "r"(addr));
}
__device__ __forceinline__ void ldm_x4t(uint32_t* r, uint32_t addr) {
    asm volatile("ldmatrix.sync.aligned.m8n8.x4.trans.shared.b16 {%0,%1,%2,%3}, [%4];"
        : "=r"(r[0]), "=r"(r[1]), "=r"(r[2]), "=r"(r[3]) : "r"(addr));
}
__device__ __forceinline__ void mma_bf16(float* d, const uint32_t* a, uint32_t b0, uint32_t b1) {
    asm volatile("mma.sync.aligned.m16n8k16.row.col.f32.bf16.bf16.f32 "
        "{%0,%1,%2,%3}, {%4,%5,%6,%7}, {%8,%9}, {%0,%1,%2,%3};"
        : "+f"(d[0]), "+f"(d[1]), "+f"(d[2]), "+f"(d[3])
        : "r"(a[0]), "r"(a[1]), "r"(a[2]), "r"(a[3]), "r"(b0), "r"(b1));
}
__device__ __forceinline__ void cp16(uint32_t saddr, const void* g) {
    asm volatile("cp.async.cg.shared.global [%0], [%1], 16;" :: "r"(saddr), "l"(g));
}
#define CP_COMMIT() asm volatile("cp.async.commit_group;" ::: "memory")
#define CP_WAIT1()  asm volatile("cp.async.wait_group 1;" ::: "memory")
#define CP_WAIT0()  asm volatile("cp.async.wait_group 0;" ::: "memory")

__device__ __forceinline__ void split_pack(float a, float b, uint32_t& hi, uint32_t& lo) {
    __nv_bfloat162 h = __floats2bfloat162_rn(a, b);
    hi = *(uint32_t*)&h;
    __nv_bfloat162 l = __floats2bfloat162_rn(a - __bfloat162float(h.x),
                                             b - __bfloat162float(h.y));
    lo = *(uint32_t*)&l;
}
__device__ __forceinline__ void split4_store(float4 v, __nv_bfloat16* hp, __nv_bfloat16* lp) {
    uint32_t h0, l0, h1, l1;
    split_pack(v.x, v.y, h0, l0);
    split_pack(v.z, v.w, h1, l1);
    *(uint2*)hp = make_uint2(h0, h1);
    *(uint2*)lp = make_uint2(l0, l1);
}

// ---------------- LayerNorm ----------------
__global__ __launch_bounds__(256)
void layernorm_kernel(const float* __restrict__ x, const float* __restrict__ w,
                      const float* __restrict__ b) {
    int s = blockIdx.x, tid = threadIdx.x;
    const float* row = x + (size_t)s * HID;
    float4 a = *(const float4*)(row + tid * 4);
    float4 c = *(const float4*)(row + 1024 + tid * 4);
    float s1 = a.x + a.y + a.z + a.w + c.x + c.y + c.z + c.w;
    float s2 = a.x*a.x + a.y*a.y + a.z*a.z + a.w*a.w
             + c.x*c.x + c.y*c.y + c.z*c.z + c.w*c.w;
    #pragma unroll
    for (int off = 16; off; off >>= 1) {
        s1 += __shfl_xor_sync(0xffffffffu, s1, off);
        s2 += __shfl_xor_sync(0xffffffffu, s2, off);
    }
    __shared__ float r1[8], r2[8];
    int wrp = tid >> 5, lane = tid & 31;
    if (lane == 0) { r1[wrp] = s1; r2[wrp] = s2; }
    __syncthreads();
    if (tid == 0) {
        float t1 = 0.f, t2 = 0.f;
        #pragma unroll
        for (int i = 0; i < 8; i++) { t1 += r1[i]; t2 += r2[i]; }
        r1[0] = t1; r2[0] = t2;
    }
    __syncthreads();
    float mu = r1[0] * (1.f / HID);
    float var = r2[0] * (1.f / HID) - mu * mu;
    float rs = rsqrtf(var + EPS);
    size_t rbase = (size_t)s * HID;
    int c0 = tid * 4;
    float4 w0 = *(const float4*)(w + c0), b0 = *(const float4*)(b + c0);
    float4 o0 = make_float4((a.x-mu)*rs*w0.x+b0.x, (a.y-mu)*rs*w0.y+b0.y,
                            (a.z-mu)*rs*w0.z+b0.z, (a.w-mu)*rs*w0.w+b0.w);
    split4_store(o0, g_lnx_hi + rbase + c0, g_lnx_lo + rbase + c0);
    int c1 = 1024 + tid * 4;
    float4 w1 = *(const float4*)(w + c1), b1 = *(const float4*)(b + c1);
    float4 o1 = make_float4((c.x-mu)*rs*w1.x+b1.x, (c.y-mu)*rs*w1.y+b1.y,
                            (c.z-mu)*rs*w1.z+b1.z, (c.w-mu)*rs*w1.w+b1.w);
    split4_store(o1, g_lnx_hi + rbase + c1, g_lnx_lo + rbase + c1);
}

__global__ __launch_bounds__(256)
void splitw_kernel(const float* __restrict__ x, int which, int n) {
    __nv_bfloat16* hi = which ? g_wproj_hi : g_wqkv_hi;
    __nv_bfloat16* lo = which ? g_wproj_lo : g_wqkv_lo;
    int i = (blockIdx.x * 256 + threadIdx.x) * 4;
    if (i < n) split4_store(*(const float4*)(x + i), hi + i, lo + i);
}

// ---------------- GEMM, templated epilogue, low register pressure ----------------
#define BK 32
#define STAGE_BYTES 32768
#define A_HI_OFF 0
#define A_LO_OFF 8192
#define B_HI_OFF 16384
#define B_LO_OFF 24576
#define GSMEM (2 * STAGE_BYTES)

template<int WHICH>
__global__ __launch_bounds__(256, 2)
void gemm_tmpl(const float* __restrict__ bias, float* __restrict__ Cout, int ldc) {
    extern __shared__ __align__(1024) char smem[];
    const __nv_bfloat16 *Ahi, *Alo, *Bhi, *Blo;
    if (WHICH == 0) { Ahi = g_lnx_hi; Alo = g_lnx_lo; Bhi = g_wqkv_hi; Blo = g_wqkv_lo; }
    else            { Ahi = g_ctx_hi; Alo = g_ctx_lo; Bhi = g_wproj_hi; Blo = g_wproj_lo; }
    const int NCHUNK = HID / BK;
    uint32_t sb = smem_u32(smem);
    int tid = threadIdx.x, wid = tid >> 5, lane = tid & 31;
    int row0 = blockIdx.y * 128, col0 = blockIdx.x * 128;
    int wm = wid >> 2, wn = wid & 3;

    int soff[2]; size_t ga[2], gb[2];
    #pragma unroll
    for (int j = 0; j < 2; j++) {
        int v = tid + j * 256;
        int r = v >> 2, c16 = v & 3, tr = r & 15;
        soff[j] = ((r >> 4) * 2 + (c16 >> 1)) * 512 + tr * 32
                + (((c16 & 1) ^ ((tr >> 2) & 1))) * 16;
        ga[j] = (size_t)(row0 + r) * HID + c16 * 8;
        gb[j] = (size_t)(col0 + r) * HID + c16 * 8;
    }
    float acc[4][4][4];
    #pragma unroll
    for (int i = 0; i < 4; i++)
        #pragma unroll
        for (int j = 0; j < 4; j++)
            #pragma unroll
            for (int q = 0; q < 4; q++) acc[i][j][q] = 0.f;
    int lr = lane & 15, lch = lane >> 4;
    int laneoff = lr * 32 + ((lch ^ ((lr >> 2) & 1))) * 16;

    #pragma unroll
    for (int c = 0; c < 2; c++) {
        uint32_t base = sb + c * STAGE_BYTES;
        int k0 = c * BK;
        #pragma unroll
        for (int j = 0; j < 2; j++) {
            cp16(base + A_HI_OFF + soff[j], Ahi + ga[j] + k0);
            cp16(base + A_LO_OFF + soff[j], Alo + ga[j] + k0);
            cp16(base + B_HI_OFF + soff[j], Bhi + gb[j] + k0);
            cp16(base + B_LO_OFF + soff[j], Blo + gb[j] + k0);
        }
        CP_COMMIT();
    }
    for (int c = 0; c < NCHUNK; c++) {
        if (c >= NCHUNK - 2) CP_WAIT0(); else CP_WAIT1();
        __syncthreads();
        uint32_t stg = sb + (c & 1) * STAGE_BYTES;
        #pragma unroll
        for (int kt = 0; kt < 2; kt++) {
            uint32_t aT0 = stg + ((wm * 4) * 2 + kt) * 512 + laneoff;
            uint32_t bT0 = stg + ((wn * 2) * 2 + kt) * 512 + laneoff;
            uint32_t bH[2][4], bL[2][4];
            #pragma unroll
            for (int j = 0; j < 2; j++) ldm_x4(bH[j], bT0 + B_HI_OFF + j * 1024);
            #pragma unroll
            for (int j = 0; j < 2; j++) ldm_x4(bL[j], bT0 + B_LO_OFF + j * 1024);
            #pragma unroll
            for (int mt = 0; mt < 4; mt++) {
                uint32_t aH[4], aL[4];
                ldm_x4(aH, aT0 + A_HI_OFF + mt * 1024);
                #pragma unroll
                for (int j = 0; j < 2; j++) {
                    mma_bf16(acc[mt][j*2+0], aH, bH[j][0], bH[j][2]);
                    mma_bf16(acc[mt][j*2+1], aH, bH[j][1], bH[j][3]);
                }
                ldm_x4(aL, aT0 + A_LO_OFF + mt * 1024);
                #pragma unroll
                for (int j = 0; j < 2; j++) {
                    mma_bf16(acc[mt][j*2+0], aH, bL[j][0], bL[j][2]);
                    mma_bf16(acc[mt][j*2+1], aH, bL[j][1], bL[j][3]);
                }
                #pragma unroll
                for (int j = 0; j < 2; j++) {
                    mma_bf16(acc[mt][j*2+0], aL, bH[j][0], bH[j][2]);
                    mma_bf16(acc[mt][j*2+1], aL, bH[j][1], bH[j][3]);
                }
            }
        }
        __syncthreads();
        if (c + 2 < NCHUNK) {
            uint32_t base = sb + (c & 1) * STAGE_BYTES;
            int k0 = (c + 2) * BK;
            #pragma unroll
            for (int j = 0; j < 2; j++) {
                cp16(base + A_HI_OFF + soff[j], Ahi + ga[j] + k0);
                cp16(base + A_LO_OFF + soff[j], Alo + ga[j] + k0);
                cp16(base + B_HI_OFF + soff[j], Bhi + gb[j] + k0);
                cp16(base + B_LO_OFF + soff[j], Blo + gb[j] + k0);
            }
            CP_COMMIT();
        }
    }
    int rg = lane >> 2, cg = (lane & 3) * 2;
    #pragma unroll
    for (int mt = 0; mt < 4; mt++) {
        int row = row0 + wm * 64 + mt * 16 + rg;
        #pragma unroll
        for (int n8 = 0; n8 < 4; n8++) {
            int col = col0 + wn * 32 + n8 * 8 + cg;
            float b0 = bias[col], b1 = bias[col + 1];
            if (WHICH == 0) {
                int seg = col >> 11, cs = col & 2047;
                float sc = (seg == 0) ? QSCALE : 1.f;
                __nv_bfloat16 *hp = (seg == 0) ? g_q_hi : (seg == 1) ? g_k_hi : g_v_hi;
                __nv_bfloat16 *lp = (seg == 0) ? g_q_lo : (seg == 1) ? g_k_lo : g_v_lo;
                uint32_t hi, lo;
                split_pack((acc[mt][n8][0]+b0)*sc, (acc[mt][n8][1]+b1)*sc, hi, lo);
                *(uint32_t*)(hp + (size_t)row * HID + cs) = hi;
                *(uint32_t*)(lp + (size_t)row * HID + cs) = lo;
                split_pack((acc[mt][n8][2]+b0)*sc, (acc[mt][n8][3]+b1)*sc, hi, lo);
                *(uint32_t*)(hp + (size_t)(row + 8) * HID + cs) = hi;
                *(uint32_t*)(lp + (size_t)(row + 8) * HID + cs) = lo;
            } else {
                *(float2*)(Cout + (size_t)row * ldc + col) =
                    make_float2(acc[mt][n8][0]+b0, acc[mt][n8][1]+b1);
                *(float2*)(Cout + (size_t)(row + 8) * ldc + col) =
                    make_float2(acc[mt][n8][2]+b0, acc[mt][n8][3]+b1);
            }
        }
    }
}

// ---------------- FA2 attention, mma.sync bf16x3 ----------------
#define QH_OFF 0
#define QL_OFF 32768
#define ST_OFF 65536
#define ST_STRIDE 65536
#define AKH 0
#define AKL 16384
#define AVH 32768
#define AVL 49152
#define ASMEM (ST_OFF + 2 * ST_STRIDE)

__global__ __launch_bounds__(256, 1)
void attn_mma_kernel() {
    extern __shared__ __align__(1024) char smem[];
    uint32_t sb = smem_u32(smem);
    int tid = threadIdx.x, wid = tid >> 5, lane = tid & 31, l15 = lane & 15;
    int h = blockIdx.y;
    int qb = (int)gridDim.x - 1 - (int)blockIdx.x;
    int q0 = qb * 128;
    int ntiles = qb * 2 + 2;
    size_t hoff = (size_t)h * HD;

    int qs[8]; size_t qg[8];
    #pragma unroll
    for (int j = 0; j < 8; j++) {
        int v = tid + j * 256;
        int r = v >> 4, c16 = v & 15, tc = c16 >> 1;
        qs[j] = ((r >> 4) * 8 + tc) * 512 + (((r & 15) ^ tc) * 32)
              + (((c16 & 1) ^ ((r >> 2) & 1)) * 16);
        qg[j] = (size_t)(q0 + r) * HID + hoff + c16 * 8;
    }
    int ks[4]; size_t kg[4];
    #pragma unroll
    for (int j = 0; j < 4; j++) {
        int v = tid + j * 256;
        int r = v >> 4, c16 = v & 15, tc = c16 >> 1;
        ks[j] = ((r >> 4) * 8 + tc) * 512 + (((r & 15) ^ tc) * 32)
              + (((c16 & 1) ^ ((r >> 2) & 1)) * 16);
        kg[j] = (size_t)r * HID + hoff + c16 * 8;
    }

    #pragma unroll
    for (int j = 0; j < 8; j++) {
        cp16(sb + QH_OFF + qs[j], g_q_hi + qg[j]);
        cp16(sb + QL_OFF + qs[j], g_q_lo + qg[j]);
    }
    CP_COMMIT();
    #pragma unroll
    for (int t = 0; t < 2; t++) {
        uint32_t stb = sb + ST_OFF + t * ST_STRIDE;
        size_t kvb = (size_t)(t * 64) * HID;
        #pragma unroll
        for (int j = 0; j < 4; j++) {
            cp16(stb + AKH + ks[j], g_k_hi + kvb + kg[j]);
            cp16(stb + AKL + ks[j], g_k_lo + kvb + kg[j]);
            cp16(stb + AVH + ks[j], g_v_hi + kvb + kg[j]);
            cp16(stb + AVL + ks[j], g_v_lo + kvb + kg[j]);
        }
        CP_COMMIT();
    }

    int slotoff = ((lane >> 4) ^ ((lane >> 2) & 1)) * 16;
    int gr = q0 + wid * 16 + (lane >> 2);
    int colb = 2 * (lane & 3);

    float o[16][4];
    #pragma unroll
    for (int i = 0; i < 16; i++)
        #pragma unroll
        for (int j = 0; j < 4; j++) o[i][j] = 0.f;
    float m0 = -INFINITY, m1 = -INFINITY, l0 = 0.f, l1 = 0.f;

    for (int t = 0; t < ntiles; t++) {
        if (t >= ntiles - 2) CP_WAIT0(); else CP_WAIT1();
        __syncthreads();
        uint32_t stb = sb + ST_OFF + (t & 1) * ST_STRIDE;
        int kt0 = t * 64;
        bool active = (q0 + wid * 16 + 15) >= kt0;

        if (active) {
            float s[8][4];
            #pragma unroll
            for (int i = 0; i < 8; i++)
                #pragma unroll
                for (int j = 0; j < 4; j++) s[i][j] = 0.f;

            #pragma unroll
            for (int kc = 0; kc < 8; kc++) {
                int tl = ((l15 ^ kc) * 32) + slotoff;
                uint32_t qh[4], ql[4], kh[4][4], kl[4][4];
                ldm_x4(qh, sb + QH_OFF + (wid * 8 + kc) * 512 + tl);
                ldm_x4(ql, sb + QL_OFF + (wid * 8 + kc) * 512 + tl);
                #pragma unroll
                for (int ng = 0; ng < 4; ng++) ldm_x4(kh[ng], stb + AKH + (ng * 8 + kc) * 512 + tl);
                #pragma unroll
                for (int ng = 0; ng < 4; ng++) ldm_x4(kl[ng], stb + AKL + (ng * 8 + kc) * 512 + tl);
                #pragma unroll
                for (int ng = 0; ng < 4; ng++) {
                    mma_bf16(s[2*ng],   qh, kh[ng][0], kh[ng][2]);
                    mma_bf16(s[2*ng+1], qh, kh[ng][1], kh[ng][3]);
                    mma_bf16(s[2*ng],   qh, kl[ng][0], kl[ng][2]);
                    mma_bf16(s[2*ng+1], qh, kl[ng][1], kl[ng][3]);
                    mma_bf16(s[2*ng],   ql, kh[ng][0], kh[ng][2]);
                    mma_bf16(s[2*ng+1], ql, kh[ng][1], kh[ng][3]);
                }
            }

            if (kt0 + 63 > gr) {
                #pragma unroll
                for (int t8 = 0; t8 < 8; t8++) {
                    int col = kt0 + t8 * 8 + colb;
                    if (col > gr)         s[t8][0] = -INFINITY;
                    if (col + 1 > gr)     s[t8][1] = -INFINITY;
                    if (col > gr + 8)     s[t8][2] = -INFINITY;
                    if (col + 1 > gr + 8) s[t8][3] = -INFINITY;
                }
            }

            float tm0 = m0, tm1 = m1;
            #pragma unroll
            for (int t8 = 0; t8 < 8; t8++) {
                tm0 = fmaxf(tm0, fmaxf(s[t8][0], s[t8][1]));
                tm1 = fmaxf(tm1, fmaxf(s[t8][2], s[t8][3]));
            }
            tm0 = fmaxf(tm0, __shfl_xor_sync(0xffffffffu, tm0, 1));
            tm0 = fmaxf(tm0, __shfl_xor_sync(0xffffffffu, tm0, 2));
            tm1 = fmaxf(tm1, __shfl_xor_sync(0xffffffffu, tm1, 1));
            tm1 = fmaxf(tm1, __shfl_xor_sync(0xffffffffu, tm1, 2));
            float c0 = __expf(m0 - tm0), c1 = __expf(m1 - tm1);
            m0 = tm0; m1 = tm1;
            float rs0 = 0.f, rs1 = 0.f;
            #pragma unroll
            for (int t8 = 0; t8 < 8; t8++) {
                s[t8][0] = __expf(s[t8][0] - m0); rs0 += s[t8][0];
                s[t8][1] = __expf(s[t8][1] - m0); rs0 += s[t8][1];
                s[t8][2] = __expf(s[t8][2] - m1); rs1 += s[t8][2];
                s[t8][3] = __expf(s[t8][3] - m1); rs1 += s[t8][3];
            }
            rs0 += __shfl_xor_sync(0xffffffffu, rs0, 1);
            rs0 += __shfl_xor_sync(0xffffffffu, rs0, 2);
            rs1 += __shfl_xor_sync(0xffffffffu, rs1, 1);
            rs1 += __shfl_xor_sync(0xffffffffu, rs1, 2);
            l0 = l0 * c0 + rs0;
            l1 = l1 * c1 + rs1;
            #pragma unroll
            for (int i = 0; i < 16; i++) {
                o[i][0] *= c0; o[i][1] *= c0; o[i][2] *= c1; o[i][3] *= c1;
            }

            #pragma unroll
            for (int kc2 = 0; kc2 < 4; kc2++) {
                uint32_t ph[4], pl[4];
                split_pack(s[2*kc2][0],   s[2*kc2][1],   ph[0], pl[0]);
                split_pack(s[2*kc2][2],   s[2*kc2][3],   ph[1], pl[1]);
                split_pack(s[2*kc2+1][0], s[2*kc2+1][1], ph[2], pl[2]);
                split_pack(s[2*kc2+1][2], s[2*kc2+1][3], ph[3], pl[3]);
                #pragma unroll
                for (int dd = 0; dd < 8; dd++) {
                    int tl = ((l15 ^ dd) * 32) + slotoff;
                    uint32_t vh[4], vl[4];
                    ldm_x4t(vh, stb + AVH + (kc2 * 8 + dd) * 512 + tl);
                    ldm_x4t(vl, stb + AVL + (kc2 * 8 + dd) * 512 + tl);
                    mma_bf16(o[dd*2],   ph, vh[0], vh[1]);
                    mma_bf16(o[dd*2+1], ph, vh[2], vh[3]);
                    mma_bf16(o[dd*2],   ph, vl[0], vl[1]);
                    mma_bf16(o[dd*2+1], ph, vl[2], vl[3]);
                    mma_bf16(o[dd*2],   pl, vh[0], vh[1]);
                    mma_bf16(o[dd*2+1], pl, vh[2], vh[3]);
                }
            }
        }
        __syncthreads();
        if (t + 2 < ntiles) {
            uint32_t stb2 = sb + ST_OFF + (t & 1) * ST_STRIDE;
            size_t kvb = (size_t)((t + 2) * 64) * HID;
            #pragma unroll
            for (int j = 0; j < 4; j++) {
                cp16(stb2 + AKH + ks[j], g_k_hi + kvb + kg[j]);
                cp16(stb2 + AKL + ks[j], g_k_lo + kvb + kg[j]);
                cp16(stb2 + AVH + ks[j], g_v_hi + kvb + kg[j]);
                cp16(stb2 + AVL + ks[j], g_v_lo + kvb + kg[j]);
            }
            CP_COMMIT();
        }
    }

    float inv0 = 1.f / l0, inv1 = 1.f / l1;
    size_t ob0 = (size_t)gr * HID + hoff + colb;
    size_t ob1 = (size_t)(gr + 8) * HID + hoff + colb;
    #pragma unroll
    for (int n8 = 0; n8 < 16; n8++) {
        uint32_t hi, lo;
        split_pack(o[n8][0] * inv0, o[n8][1] * inv0, hi, lo);
        *(uint32_t*)(g_ctx_hi + ob0 + n8 * 8) = hi;
        *(uint32_t*)(g_ctx_lo + ob0 + n8 * 8) = lo;
        split_pack(o[n8][2] * inv1, o[n8][3] * inv1, hi, lo);
        *(uint32_t*)(g_ctx_hi + ob1 + n8 * 8) = hi;
        *(uint32_t*)(g_ctx_lo + ob1 + n8 * 8) = lo;
    }
}

extern "C" void kernel_launch(void* const* d_in, const int* in_sizes, int n_in,
                              void* d_out, int out_size) {
    const float* hs   = (const float*)d_in[0];
    const float* lw   = (const float*)d_in[1];
    const float* lb   = (const float*)d_in[2];
    const float* qkvw = (const float*)d_in[3];
    const float* qkvb = (const float*)d_in[4];
    const float* pw   = (const float*)d_in[5];
    const float* pb   = (const float*)d_in[6];
    float* out = (float*)d_out;

    cudaFuncSetAttribute(gemm_tmpl<0>, cudaFuncAttributeMaxDynamicSharedMemorySize, GSMEM);
    cudaFuncSetAttribute(gemm_tmpl<1>, cudaFuncAttributeMaxDynamicSharedMemorySize, GSMEM);
    cudaFuncSetAttribute(attn_mma_kernel, cudaFuncAttributeMaxDynamicSharedMemorySize, ASMEM);

    layernorm_kernel<<<S_LEN, 256>>>(hs, lw, lb);
    splitw_kernel<<<(QKV_N * HID / 4) / 256, 256>>>(qkvw, 0, QKV_N * HID);
    splitw_kernel<<<(HID * HID / 4) / 256, 256>>>(pw, 1, HID * HID);
    gemm_tmpl<0><<<dim3(QKV_N / 128, S_LEN / 128), 256, GSMEM>>>(qkvb, nullptr, QKV_N);
    attn_mma_kernel<<<dim3(S_LEN / 128, NH), 256, ASMEM>>>();
    gemm_tmpl<1><<<dim3(HID / 128, S_LEN / 128), 256, GSMEM>>>(pb, out, HID);
}

// round 10
// speedup vs baseline: 3.5126x; 1.0217x over previous
#include <cuda_runtime.h>
#include <cuda_bf16.h>
#include <math.h>
#include <stdint.h>

#define S_LEN 2048
#define HID   2048
#define NH    16
#define HD    128
#define QKV_N 6144
#define EPS   1e-5f
#define QSCALE 0.08838834764831845f

__device__ __nv_bfloat16 g_lnx_hi [S_LEN * HID];
__device__ __nv_bfloat16 g_lnx_lo [S_LEN * HID];
__device__ __nv_bfloat16 g_wqkv_hi[QKV_N * HID];
__device__ __nv_bfloat16 g_wqkv_lo[QKV_N * HID];
__device__ __nv_bfloat16 g_wproj_hi[HID * HID];
__device__ __nv_bfloat16 g_wproj_lo[HID * HID];
__device__ __nv_bfloat16 g_q_hi[S_LEN * HID];
__device__ __nv_bfloat16 g_q_lo[S_LEN * HID];
__device__ __nv_bfloat16 g_k_hi[S_LEN * HID];
__device__ __nv_bfloat16 g_k_lo[S_LEN * HID];
__device__ __nv_bfloat16 g_v_hi[S_LEN * HID];
__device__ __nv_bfloat16 g_v_lo[S_LEN * HID];
__device__ __nv_bfloat16 g_ctx_hi[S_LEN * HID];
__device__ __nv_bfloat16 g_ctx_lo[S_LEN * HID];

__device__ __forceinline__ uint32_t smem_u32(const void* p) {
    uint32_t a;
    asm("{ .reg .u64 t; cvta.to.shared.u64 t, %1; cvt.u32.u64 %0, t; }" : "=r"(a) : "l"(p));
    return a;
}
__device__ __forceinline__ void ldm_x4(uint32_t* r, uint32_t addr) {
    asm volatile("ldmatrix.sync.aligned.m8n8.x4.shared.b16 {%0,%1,%2,%3}, [%4];"
        : "=r"(r[0]), "=r"(r[1]), "=r"(r[2]), "=r"(r[3]) : "r"(addr));
}
__device__ __forceinline__ void ldm_x4t(uint32_t* r, uint32_t addr) {
    asm volatile("ldmatrix.sync.aligned.m8n8.x4.trans.shared.b16 {%0,%1,%2,%3}, [%4];"
        : "=r"(r[0]), "=r"(r[1]), "=r"(r[2]), "=r"(r[3]) : "r"(addr));
}
__device__ __forceinline__ void mma_bf16(float* d, const uint32_t* a, uint32_t b0, uint32_t b1) {
    asm volatile("mma.sync.aligned.m16n8k16.row.col.f32.bf16.bf16.f32 "
        "{%0,%1,%2,%3}, {%4,%5,%6,%7}, {%8,%9}, {%0,%1,%2,%3};"
        : "+f"(d[0]), "+f"(d[1]), "+f"(d[2]), "+f"(d[3])
        : "r"(a[0]), "r"(a[1]), "r"(a[2]), "r"(a[3]), "r"(b0), "r"(b1));
}
__device__ __forceinline__ void cp16(uint32_t saddr, const void* g) {
    asm volatile("cp.async.cg.shared.global [%0], [%1], 16;" :: "r"(saddr), "l"(g));
}
#define CP_COMMIT() asm volatile("cp.async.commit_group;" ::: "memory")
#define CP_WAIT1()  asm volatile("cp.async.wait_group 1;" ::: "memory")
#define CP_WAIT0()  asm volatile("cp.async.wait_group 0;" ::: "memory")

__device__ __forceinline__ void split_pack(float a, float b, uint32_t& hi, uint32_t& lo) {
    __nv_bfloat162 h = __floats2bfloat162_rn(a, b);
    hi = *(uint32_t*)&h;
    __nv_bfloat162 l = __floats2bfloat162_rn(a - __bfloat162float(h.x),
                                             b - __bfloat162float(h.y));
    lo = *(uint32_t*)&l;
}
__device__ __forceinline__ void split4_store(float4 v, __nv_bfloat16* hp, __nv_bfloat16* lp) {
    uint32_t h0, l0, h1, l1;
    split_pack(v.x, v.y, h0, l0);
    split_pack(v.z, v.w, h1, l1);
    *(uint2*)hp = make_uint2(h0, h1);
    *(uint2*)lp = make_uint2(l0, l1);
}

// ---------------- LayerNorm ----------------
__global__ __launch_bounds__(256)
void layernorm_kernel(const float* __restrict__ x, const float* __restrict__ w,
                      const float* __restrict__ b) {
    int s = blockIdx.x, tid = threadIdx.x;
    const float* row = x + (size_t)s * HID;
    float4 a = *(const float4*)(row + tid * 4);
    float4 c = *(const float4*)(row + 1024 + tid * 4);
    float s1 = a.x + a.y + a.z + a.w + c.x + c.y + c.z + c.w;
    float s2 = a.x*a.x + a.y*a.y + a.z*a.z + a.w*a.w
             + c.x*c.x + c.y*c.y + c.z*c.z + c.w*c.w;
    #pragma unroll
    for (int off = 16; off; off >>= 1) {
        s1 += __shfl_xor_sync(0xffffffffu, s1, off);
        s2 += __shfl_xor_sync(0xffffffffu, s2, off);
    }
    __shared__ float r1[8], r2[8];
    int wrp = tid >> 5, lane = tid & 31;
    if (lane == 0) { r1[wrp] = s1; r2[wrp] = s2; }
    __syncthreads();
    if (tid == 0) {
        float t1 = 0.f, t2 = 0.f;
        #pragma unroll
        for (int i = 0; i < 8; i++) { t1 += r1[i]; t2 += r2[i]; }
        r1[0] = t1; r2[0] = t2;
    }
    __syncthreads();
    float mu = r1[0] * (1.f / HID);
    float var = r2[0] * (1.f / HID) - mu * mu;
    float rs = rsqrtf(var + EPS);
    size_t rbase = (size_t)s * HID;
    int c0 = tid * 4;
    float4 w0 = *(const float4*)(w + c0), b0 = *(const float4*)(b + c0);
    float4 o0 = make_float4((a.x-mu)*rs*w0.x+b0.x, (a.y-mu)*rs*w0.y+b0.y,
                            (a.z-mu)*rs*w0.z+b0.z, (a.w-mu)*rs*w0.w+b0.w);
    split4_store(o0, g_lnx_hi + rbase + c0, g_lnx_lo + rbase + c0);
    int c1 = 1024 + tid * 4;
    float4 w1 = *(const float4*)(w + c1), b1 = *(const float4*)(b + c1);
    float4 o1 = make_float4((c.x-mu)*rs*w1.x+b1.x, (c.y-mu)*rs*w1.y+b1.y,
                            (c.z-mu)*rs*w1.z+b1.z, (c.w-mu)*rs*w1.w+b1.w);
    split4_store(o1, g_lnx_hi + rbase + c1, g_lnx_lo + rbase + c1);
}

__global__ __launch_bounds__(256)
void splitw_kernel(const float* __restrict__ x, int which, int n) {
    __nv_bfloat16* hi = which ? g_wproj_hi : g_wqkv_hi;
    __nv_bfloat16* lo = which ? g_wproj_lo : g_wqkv_lo;
    int i = (blockIdx.x * 256 + threadIdx.x) * 4;
    if (i < n) split4_store(*(const float4*)(x + i), hi + i, lo + i);
}

// ---------------- GEMM: 3-stage cp.async pipeline, 1 barrier/chunk ----------------
#define BK 32
#define STAGE_BYTES 32768
#define A_HI_OFF 0
#define A_LO_OFF 8192
#define B_HI_OFF 16384
#define B_LO_OFF 24576
#define GSMEM (3 * STAGE_BYTES)

template<int WHICH>
__global__ __launch_bounds__(256, 2)
void gemm_tmpl(const float* __restrict__ bias, float* __restrict__ Cout, int ldc) {
    extern __shared__ __align__(1024) char smem[];
    const __nv_bfloat16 *Ahi, *Alo, *Bhi, *Blo;
    if (WHICH == 0) { Ahi = g_lnx_hi; Alo = g_lnx_lo; Bhi = g_wqkv_hi; Blo = g_wqkv_lo; }
    else            { Ahi = g_ctx_hi; Alo = g_ctx_lo; Bhi = g_wproj_hi; Blo = g_wproj_lo; }
    const int NCHUNK = HID / BK;   // 64
    uint32_t sb = smem_u32(smem);
    int tid = threadIdx.x, wid = tid >> 5, lane = tid & 31;
    int row0 = blockIdx.y * 128, col0 = blockIdx.x * 128;
    int wm = wid >> 2, wn = wid & 3;

    int soff[2]; size_t ga[2], gb[2];
    #pragma unroll
    for (int j = 0; j < 2; j++) {
        int v = tid + j * 256;
        int r = v >> 2, c16 = v & 3, tr = r & 15;
        soff[j] = ((r >> 4) * 2 + (c16 >> 1)) * 512 + tr * 32
                + (((c16 & 1) ^ ((tr >> 2) & 1))) * 16;
        ga[j] = (size_t)(row0 + r) * HID + c16 * 8;
        gb[j] = (size_t)(col0 + r) * HID + c16 * 8;
    }
    float acc[4][4][4];
    #pragma unroll
    for (int i = 0; i < 4; i++)
        #pragma unroll
        for (int j = 0; j < 4; j++)
            #pragma unroll
            for (int q = 0; q < 4; q++) acc[i][j][q] = 0.f;
    int lr = lane & 15, lch = lane >> 4;
    int laneoff = lr * 32 + ((lch ^ ((lr >> 2) & 1))) * 16;

    // prologue: chunks 0,1 into buffers 0,1
    #pragma unroll
    for (int c = 0; c < 2; c++) {
        uint32_t base = sb + c * STAGE_BYTES;
        int k0 = c * BK;
        #pragma unroll
        for (int j = 0; j < 2; j++) {
            cp16(base + A_HI_OFF + soff[j], Ahi + ga[j] + k0);
            cp16(base + A_LO_OFF + soff[j], Alo + ga[j] + k0);
            cp16(base + B_HI_OFF + soff[j], Bhi + gb[j] + k0);
            cp16(base + B_LO_OFF + soff[j], Blo + gb[j] + k0);
        }
        CP_COMMIT();
    }

    int buf = 0, bpre = 2;   // buf = c%3, bpre = (c+2)%3
    for (int c = 0; c < NCHUNK; c++) {
        if (c == NCHUNK - 1) CP_WAIT0(); else CP_WAIT1();
        __syncthreads();
        // prefetch chunk c+2 into the buffer freed by chunk c-1
        if (c + 2 < NCHUNK) {
            uint32_t base = sb + bpre * STAGE_BYTES;
            int k0 = (c + 2) * BK;
            #pragma unroll
            for (int j = 0; j < 2; j++) {
                cp16(base + A_HI_OFF + soff[j], Ahi + ga[j] + k0);
                cp16(base + A_LO_OFF + soff[j], Alo + ga[j] + k0);
                cp16(base + B_HI_OFF + soff[j], Bhi + gb[j] + k0);
                cp16(base + B_LO_OFF + soff[j], Blo + gb[j] + k0);
            }
            CP_COMMIT();
        }
        uint32_t stg = sb + buf * STAGE_BYTES;
        #pragma unroll
        for (int kt = 0; kt < 2; kt++) {
            uint32_t aT0 = stg + ((wm * 4) * 2 + kt) * 512 + laneoff;
            uint32_t bT0 = stg + ((wn * 2) * 2 + kt) * 512 + laneoff;
            uint32_t bH[2][4], bL[2][4];
            #pragma unroll
            for (int j = 0; j < 2; j++) ldm_x4(bH[j], bT0 + B_HI_OFF + j * 1024);
            #pragma unroll
            for (int j = 0; j < 2; j++) ldm_x4(bL[j], bT0 + B_LO_OFF + j * 1024);
            #pragma unroll
            for (int mt = 0; mt < 4; mt++) {
                uint32_t aH[4], aL[4];
                ldm_x4(aH, aT0 + A_HI_OFF + mt * 1024);
                #pragma unroll
                for (int j = 0; j < 2; j++) {
                    mma_bf16(acc[mt][j*2+0], aH, bH[j][0], bH[j][2]);
                    mma_bf16(acc[mt][j*2+1], aH, bH[j][1], bH[j][3]);
                }
                ldm_x4(aL, aT0 + A_LO_OFF + mt * 1024);
                #pragma unroll
                for (int j = 0; j < 2; j++) {
                    mma_bf16(acc[mt][j*2+0], aH, bL[j][0], bL[j][2]);
                    mma_bf16(acc[mt][j*2+1], aH, bL[j][1], bL[j][3]);
                }
                #pragma unroll
                for (int j = 0; j < 2; j++) {
                    mma_bf16(acc[mt][j*2+0], aL, bH[j][0], bH[j][2]);
                    mma_bf16(acc[mt][j*2+1], aL, bH[j][1], bH[j][3]);
                }
            }
        }
        buf = (buf == 2) ? 0 : buf + 1;
        bpre = (bpre == 2) ? 0 : bpre + 1;
    }

    int rg = lane >> 2, cg = (lane & 3) * 2;
    #pragma unroll
    for (int mt = 0; mt < 4; mt++) {
        int row = row0 + wm * 64 + mt * 16 + rg;
        #pragma unroll
        for (int n8 = 0; n8 < 4; n8++) {
            int col = col0 + wn * 32 + n8 * 8 + cg;
            float b0 = bias[col], b1 = bias[col + 1];
            if (WHICH == 0) {
                int seg = col >> 11, cs = col & 2047;
                float sc = (seg == 0) ? QSCALE : 1.f;
                __nv_bfloat16 *hp = (seg == 0) ? g_q_hi : (seg == 1) ? g_k_hi : g_v_hi;
                __nv_bfloat16 *lp = (seg == 0) ? g_q_lo : (seg == 1) ? g_k_lo : g_v_lo;
                uint32_t hi, lo;
                split_pack((acc[mt][n8][0]+b0)*sc, (acc[mt][n8][1]+b1)*sc, hi, lo);
                *(uint32_t*)(hp + (size_t)row * HID + cs) = hi;
                *(uint32_t*)(lp + (size_t)row * HID + cs) = lo;
                split_pack((acc[mt][n8][2]+b0)*sc, (acc[mt][n8][3]+b1)*sc, hi, lo);
                *(uint32_t*)(hp + (size_t)(row + 8) * HID + cs) = hi;
                *(uint32_t*)(lp + (size_t)(row + 8) * HID + cs) = lo;
            } else {
                *(float2*)(Cout + (size_t)row * ldc + col) =
                    make_float2(acc[mt][n8][0]+b0, acc[mt][n8][1]+b1);
                *(float2*)(Cout + (size_t)(row + 8) * ldc + col) =
                    make_float2(acc[mt][n8][2]+b0, acc[mt][n8][3]+b1);
            }
        }
    }
}

// ---------------- FA2 attention, mma.sync bf16x3 ----------------
#define QH_OFF 0
#define QL_OFF 32768
#define ST_OFF 65536
#define ST_STRIDE 65536
#define AKH 0
#define AKL 16384
#define AVH 32768
#define AVL 49152
#define ASMEM (ST_OFF + 2 * ST_STRIDE)

__global__ __launch_bounds__(256, 1)
void attn_mma_kernel() {
    extern __shared__ __align__(1024) char smem[];
    uint32_t sb = smem_u32(smem);
    int tid = threadIdx.x, wid = tid >> 5, lane = tid & 31, l15 = lane & 15;
    int h = blockIdx.y;
    int qb = (int)gridDim.x - 1 - (int)blockIdx.x;
    int q0 = qb * 128;
    int ntiles = qb * 2 + 2;
    size_t hoff = (size_t)h * HD;

    int qs[8]; size_t qg[8];
    #pragma unroll
    for (int j = 0; j < 8; j++) {
        int v = tid + j * 256;
        int r = v >> 4, c16 = v & 15, tc = c16 >> 1;
        qs[j] = ((r >> 4) * 8 + tc) * 512 + (((r & 15) ^ tc) * 32)
              + (((c16 & 1) ^ ((r >> 2) & 1)) * 16);
        qg[j] = (size_t)(q0 + r) * HID + hoff + c16 * 8;
    }
    int ks[4]; size_t kg[4];
    #pragma unroll
    for (int j = 0; j < 4; j++) {
        int v = tid + j * 256;
        int r = v >> 4, c16 = v & 15, tc = c16 >> 1;
        ks[j] = ((r >> 4) * 8 + tc) * 512 + (((r & 15) ^ tc) * 32)
              + (((c16 & 1) ^ ((r >> 2) & 1)) * 16);
        kg[j] = (size_t)r * HID + hoff + c16 * 8;
    }

    #pragma unroll
    for (int j = 0; j < 8; j++) {
        cp16(sb + QH_OFF + qs[j], g_q_hi + qg[j]);
        cp16(sb + QL_OFF + qs[j], g_q_lo + qg[j]);
    }
    CP_COMMIT();
    #pragma unroll
    for (int t = 0; t < 2; t++) {
        uint32_t stb = sb + ST_OFF + t * ST_STRIDE;
        size_t kvb = (size_t)(t * 64) * HID;
        #pragma unroll
        for (int j = 0; j < 4; j++) {
            cp16(stb + AKH + ks[j], g_k_hi + kvb + kg[j]);
            cp16(stb + AKL + ks[j], g_k_lo + kvb + kg[j]);
            cp16(stb + AVH + ks[j], g_v_hi + kvb + kg[j]);
            cp16(stb + AVL + ks[j], g_v_lo + kvb + kg[j]);
        }
        CP_COMMIT();
    }

    int slotoff = ((lane >> 4) ^ ((lane >> 2) & 1)) * 16;
    int gr = q0 + wid * 16 + (lane >> 2);
    int colb = 2 * (lane & 3);

    float o[16][4];
    #pragma unroll
    for (int i = 0; i < 16; i++)
        #pragma unroll
        for (int j = 0; j < 4; j++) o[i][j] = 0.f;
    float m0 = -INFINITY, m1 = -INFINITY, l0 = 0.f, l1 = 0.f;

    for (int t = 0; t < ntiles; t++) {
        if (t >= ntiles - 2) CP_WAIT0(); else CP_WAIT1();
        __syncthreads();
        uint32_t stb = sb + ST_OFF + (t & 1) * ST_STRIDE;
        int kt0 = t * 64;
        bool active = (q0 + wid * 16 + 15) >= kt0;

        if (active) {
            float s[8][4];
            #pragma unroll
            for (int i = 0; i < 8; i++)
                #pragma unroll
                for (int j = 0; j < 4; j++) s[i][j] = 0.f;

            #pragma unroll
            for (int kc = 0; kc < 8; kc++) {
                int tl = ((l15 ^ kc) * 32) + slotoff;
                uint32_t qh[4], ql[4], kh[4][4], kl[4][4];
                ldm_x4(qh, sb + QH_OFF + (wid * 8 + kc) * 512 + tl);
                ldm_x4(ql, sb + QL_OFF + (wid * 8 + kc) * 512 + tl);
                #pragma unroll
                for (int ng = 0; ng < 4; ng++) ldm_x4(kh[ng], stb + AKH + (ng * 8 + kc) * 512 + tl);
                #pragma unroll
                for (int ng = 0; ng < 4; ng++) ldm_x4(kl[ng], stb + AKL + (ng * 8 + kc) * 512 + tl);
                #pragma unroll
                for (int ng = 0; ng < 4; ng++) {
                    mma_bf16(s[2*ng],   qh, kh[ng][0], kh[ng][2]);
                    mma_bf16(s[2*ng+1], qh, kh[ng][1], kh[ng][3]);
                    mma_bf16(s[2*ng],   qh, kl[ng][0], kl[ng][2]);
                    mma_bf16(s[2*ng+1], qh, kl[ng][1], kl[ng][3]);
                    mma_bf16(s[2*ng],   ql, kh[ng][0], kh[ng][2]);
                    mma_bf16(s[2*ng+1], ql, kh[ng][1], kh[ng][3]);
                }
            }

            if (kt0 + 63 > gr) {
                #pragma unroll
                for (int t8 = 0; t8 < 8; t8++) {
                    int col = kt0 + t8 * 8 + colb;
                    if (col > gr)         s[t8][0] = -INFINITY;
                    if (col + 1 > gr)     s[t8][1] = -INFINITY;
                    if (col > gr + 8)     s[t8][2] = -INFINITY;
                    if (col + 1 > gr + 8) s[t8][3] = -INFINITY;
                }
            }

            float tm0 = m0, tm1 = m1;
            #pragma unroll
            for (int t8 = 0; t8 < 8; t8++) {
                tm0 = fmaxf(tm0, fmaxf(s[t8][0], s[t8][1]));
                tm1 = fmaxf(tm1, fmaxf(s[t8][2], s[t8][3]));
            }
            tm0 = fmaxf(tm0, __shfl_xor_sync(0xffffffffu, tm0, 1));
            tm0 = fmaxf(tm0, __shfl_xor_sync(0xffffffffu, tm0, 2));
            tm1 = fmaxf(tm1, __shfl_xor_sync(0xffffffffu, tm1, 1));
            tm1 = fmaxf(tm1, __shfl_xor_sync(0xffffffffu, tm1, 2));
            float c0 = __expf(m0 - tm0), c1 = __expf(m1 - tm1);
            m0 = tm0; m1 = tm1;
            float rs0 = 0.f, rs1 = 0.f;
            #pragma unroll
            for (int t8 = 0; t8 < 8; t8++) {
                s[t8][0] = __expf(s[t8][0] - m0); rs0 += s[t8][0];
                s[t8][1] = __expf(s[t8][1] - m0); rs0 += s[t8][1];
                s[t8][2] = __expf(s[t8][2] - m1); rs1 += s[t8][2];
                s[t8][3] = __expf(s[t8][3] - m1); rs1 += s[t8][3];
            }
            rs0 += __shfl_xor_sync(0xffffffffu, rs0, 1);
            rs0 += __shfl_xor_sync(0xffffffffu, rs0, 2);
            rs1 += __shfl_xor_sync(0xffffffffu, rs1, 1);
            rs1 += __shfl_xor_sync(0xffffffffu, rs1, 2);
            l0 = l0 * c0 + rs0;
            l1 = l1 * c1 + rs1;
            #pragma unroll
            for (int i = 0; i < 16; i++) {
                o[i][0] *= c0; o[i][1] *= c0; o[i][2] *= c1; o[i][3] *= c1;
            }

            #pragma unroll
            for (int kc2 = 0; kc2 < 4; kc2++) {
                uint32_t ph[4], pl[4];
                split_pack(s[2*kc2][0],   s[2*kc2][1],   ph[0], pl[0]);
                split_pack(s[2*kc2][2],   s[2*kc2][3],   ph[1], pl[1]);
                split_pack(s[2*kc2+1][0], s[2*kc2+1][1], ph[2], pl[2]);
                split_pack(s[2*kc2+1][2], s[2*kc2+1][3], ph[3], pl[3]);
                #pragma unroll
                for (int dd = 0; dd < 8; dd++) {
                    int tl = ((l15 ^ dd) * 32) + slotoff;
                    uint32_t vh[4], vl[4];
                    ldm_x4t(vh, stb + AVH + (kc2 * 8 + dd) * 512 + tl);
                    ldm_x4t(vl, stb + AVL + (kc2 * 8 + dd) * 512 + tl);
                    mma_bf16(o[dd*2],   ph, vh[0], vh[1]);
                    mma_bf16(o[dd*2+1], ph, vh[2], vh[3]);
                    mma_bf16(o[dd*2],   ph, vl[0], vl[1]);
                    mma_bf16(o[dd*2+1], ph, vl[2], vl[3]);
                    mma_bf16(o[dd*2],   pl, vh[0], vh[1]);
                    mma_bf16(o[dd*2+1], pl, vh[2], vh[3]);
                }
            }
        }
        __syncthreads();
        if (t + 2 < ntiles) {
            uint32_t stb2 = sb + ST_OFF + (t & 1) * ST_STRIDE;
            size_t kvb = (size_t)((t + 2) * 64) * HID;
            #pragma unroll
            for (int j = 0; j < 4; j++) {
                cp16(stb2 + AKH + ks[j], g_k_hi + kvb + kg[j]);
                cp16(stb2 + AKL + ks[j], g_k_lo + kvb + kg[j]);
                cp16(stb2 + AVH + ks[j], g_v_hi + kvb + kg[j]);
                cp16(stb2 + AVL + ks[j], g_v_lo + kvb + kg[j]);
            }
            CP_COMMIT();
        }
    }

    float inv0 = 1.f / l0, inv1 = 1.f / l1;
    size_t ob0 = (size_t)gr * HID + hoff + colb;
    size_t ob1 = (size_t)(gr + 8) * HID + hoff + colb;
    #pragma unroll
    for (int n8 = 0; n8 < 16; n8++) {
        uint32_t hi, lo;
        split_pack(o[n8][0] * inv0, o[n8][1] * inv0, hi, lo);
        *(uint32_t*)(g_ctx_hi + ob0 + n8 * 8) = hi;
        *(uint32_t*)(g_ctx_lo + ob0 + n8 * 8) = lo;
        split_pack(o[n8][2] * inv1, o[n8][3] * inv1, hi, lo);
        *(uint32_t*)(g_ctx_hi + ob1 + n8 * 8) = hi;
        *(uint32_t*)(g_ctx_lo + ob1 + n8 * 8) = lo;
    }
}

extern "C" void kernel_launch(void* const* d_in, const int* in_sizes, int n_in,
                              void* d_out, int out_size) {
    const float* hs   = (const float*)d_in[0];
    const float* lw   = (const float*)d_in[1];
    const float* lb   = (const float*)d_in[2];
    const float* qkvw = (const float*)d_in[3];
    const float* qkvb = (const float*)d_in[4];
    const float* pw   = (const float*)d_in[5];
    const float* pb   = (const float*)d_in[6];
    float* out = (float*)d_out;

    cudaFuncSetAttribute(gemm_tmpl<0>, cudaFuncAttributeMaxDynamicSharedMemorySize, GSMEM);
    cudaFuncSetAttribute(gemm_tmpl<1>, cudaFuncAttributeMaxDynamicSharedMemorySize, GSMEM);
    cudaFuncSetAttribute(attn_mma_kernel, cudaFuncAttributeMaxDynamicSharedMemorySize, ASMEM);

    layernorm_kernel<<<S_LEN, 256>>>(hs, lw, lb);
    splitw_kernel<<<(QKV_N * HID / 4) / 256, 256>>>(qkvw, 0, QKV_N * HID);
    splitw_kernel<<<(HID * HID / 4) / 256, 256>>>(pw, 1, HID * HID);
    gemm_tmpl<0><<<dim3(QKV_N / 128, S_LEN / 128), 256, GSMEM>>>(qkvb, nullptr, QKV_N);
    attn_mma_kernel<<<dim3(S_LEN / 128, NH), 256, ASMEM>>>();
    gemm_tmpl<1><<<dim3(HID / 128, S_LEN / 128), 256, GSMEM>>>(pb, out, HID);
}